// round 8
// baseline (speedup 1.0000x reference)
#include <cuda_runtime.h>
#include <math.h>
#include <stdint.h>

#define S_TOT 7681
#define C_DIM 256

// ---------------- scratch (static device globals; no allocation) ----------
__device__ float g_q   [S_TOT * C_DIM];
__device__ float g_val [S_TOT * C_DIM];
__device__ float g_off [S_TOT * C_DIM];
__device__ float g_attn[S_TOT * 128];
__device__ float g_samp[S_TOT * C_DIM];
__device__ float g_tmp [S_TOT * C_DIM];
__device__ float g_tmp2[S_TOT * C_DIM];
__device__ float g_ffh [S_TOT * 1024];

__constant__ int c_H [4] = {76, 38, 19, 10};
__constant__ int c_W [4] = {76, 38, 19, 10};
__constant__ int c_ST[4] = {0, 5776, 7220, 7581};

// ---------------- elementwise -------------------------------------------
__global__ __launch_bounds__(256) void copy_kernel(float* __restrict__ dst,
                                                   const float* __restrict__ src) {
    int i = blockIdx.x * 256 + threadIdx.x;
    dst[i] = src[i];
}

__global__ __launch_bounds__(256) void add_kernel(float* __restrict__ dst,
                                                  const float* __restrict__ a,
                                                  const float* __restrict__ b) {
    int i = blockIdx.x * 256 + threadIdx.x;
    dst[i] = a[i] + b[i];
}

// ---------------- tf32 tensor-core GEMM primitives ------------------------
__device__ __forceinline__ void cp16(uint32_t s, const void* g) {
    asm volatile("cp.async.cg.shared.global [%0], [%1], 16;" :: "r"(s), "l"(g) : "memory");
}

__device__ __forceinline__ void mma8(float c[4], const uint32_t a[4], const uint32_t b[2]) {
    asm volatile(
        "mma.sync.aligned.m16n8k8.row.col.f32.tf32.tf32.f32 "
        "{%0,%1,%2,%3}, {%4,%5,%6,%7}, {%8,%9}, {%0,%1,%2,%3};"
        : "+f"(c[0]), "+f"(c[1]), "+f"(c[2]), "+f"(c[3])
        : "r"(a[0]), "r"(a[1]), "r"(a[2]), "r"(a[3]), "r"(b[0]), "r"(b[1]));
}

// Core mainloop + epilogue, shared by all GEMM kernels.
template<int BM, int BN, int RELU>
__device__ __forceinline__ void gemm_body(
    const float* __restrict__ A, const float* __restrict__ B,
    const float* __restrict__ bias, float* __restrict__ C,
    int M, int N, int K, int lda, int m0, int n0, int use_bias,
    float (*As)[BM][20], float (*Bs)[16][BN + 4])
{
    constexpr int BK = 16;
    constexpr int WM = BM / 32;
    constexpr int WN = 8 / WM;
    constexpr int NT = BN / (WN * 8);
    constexpr int BROW = BN / 4;
    constexpr int A_ITERS = BM * 4 / 256;
    constexpr int B_ITERS = BN / 64;

    const int tid  = threadIdx.x;
    const int lane = tid & 31;
    const int wid  = tid >> 5;
    const int wm   = wid % WM;
    const int wn   = wid / WM;

    float acc[2][NT][4];
    #pragma unroll
    for (int mt = 0; mt < 2; mt++)
        #pragma unroll
        for (int nt = 0; nt < NT; nt++)
            #pragma unroll
            for (int j = 0; j < 4; j++) acc[mt][nt][j] = 0.f;

    auto prefetch = [&](int buf, int k0) {
        #pragma unroll
        for (int i = 0; i < A_ITERS; i++) {
            int f = tid + i * 256;
            int r = f >> 2, c = (f & 3) * 4;
            int gm = m0 + r; if (gm > M - 1) gm = M - 1;
            cp16((uint32_t)__cvta_generic_to_shared(&As[buf][r][c]),
                 A + (size_t)gm * lda + k0 + c);
        }
        #pragma unroll
        for (int i = 0; i < B_ITERS; i++) {
            int f = tid + i * 256;
            int r = f / BROW, c = (f % BROW) * 4;
            cp16((uint32_t)__cvta_generic_to_shared(&Bs[buf][r][c]),
                 B + (size_t)(k0 + r) * N + n0 + c);
        }
        asm volatile("cp.async.commit_group;" ::: "memory");
    };

    prefetch(0, 0);
    int buf = 0;
    for (int k0 = 0; k0 < K; k0 += BK) {
        const bool has_next = (k0 + BK) < K;
        if (has_next) {
            prefetch(buf ^ 1, k0 + BK);
            asm volatile("cp.async.wait_group 1;" ::: "memory");
        } else {
            asm volatile("cp.async.wait_group 0;" ::: "memory");
        }
        __syncthreads();

        #pragma unroll
        for (int kc = 0; kc < BK; kc += 8) {
            const int mb = wm * 32 + (lane >> 2);
            const int kk = kc + (lane & 3);
            uint32_t afr[2][4];
            #pragma unroll
            for (int mt = 0; mt < 2; mt++) {
                afr[mt][0] = __float_as_uint(As[buf][mb + mt * 16    ][kk]);
                afr[mt][1] = __float_as_uint(As[buf][mb + mt * 16 + 8][kk]);
                afr[mt][2] = __float_as_uint(As[buf][mb + mt * 16    ][kk + 4]);
                afr[mt][3] = __float_as_uint(As[buf][mb + mt * 16 + 8][kk + 4]);
            }
            uint32_t bfr[NT][2];
            #pragma unroll
            for (int nt = 0; nt < NT; nt++) {
                const int kr = kc + (lane & 3);
                const int nc = wn * (BN / WN) + nt * 8 + (lane >> 2);
                bfr[nt][0] = __float_as_uint(Bs[buf][kr    ][nc]);
                bfr[nt][1] = __float_as_uint(Bs[buf][kr + 4][nc]);
            }
            #pragma unroll
            for (int mt = 0; mt < 2; mt++)
                #pragma unroll
                for (int nt = 0; nt < NT; nt++)
                    mma8(acc[mt][nt], afr[mt], bfr[nt]);
        }
        __syncthreads();
        buf ^= 1;
    }

    #pragma unroll
    for (int mt = 0; mt < 2; mt++) {
        int gm = m0 + wm * 32 + mt * 16 + (lane >> 2);
        #pragma unroll
        for (int nt = 0; nt < NT; nt++) {
            int gn = n0 + wn * (BN / WN) + nt * 8 + 2 * (lane & 3);
            float b0 = 0.f, b1 = 0.f;
            if (use_bias) { b0 = bias[gn]; b1 = bias[gn + 1]; }
            float v0 = acc[mt][nt][0] + b0, v1 = acc[mt][nt][1] + b1;
            float v2 = acc[mt][nt][2] + b0, v3 = acc[mt][nt][3] + b1;
            if (RELU) {
                v0 = fmaxf(v0, 0.f); v1 = fmaxf(v1, 0.f);
                v2 = fmaxf(v2, 0.f); v3 = fmaxf(v3, 0.f);
            }
            if (gm < M)
                *reinterpret_cast<float2*>(C + (size_t)gm * N + gn) = make_float2(v0, v1);
            if (gm + 8 < M)
                *reinterpret_cast<float2*>(C + (size_t)(gm + 8) * N + gn) = make_float2(v2, v3);
        }
    }
}

// Plain GEMM (used for ff1): C = A@B + bias (+relu)
template<int BM, int BN, int RELU>
__global__ __launch_bounds__(256) void gemm_tf32_kernel(
    const float* __restrict__ A, const float* __restrict__ B,
    const float* __restrict__ bias, float* __restrict__ C,
    int M, int N, int K)
{
    __shared__ float As[2][BM][20];
    __shared__ float Bs[2][16][BN + 4];
    gemm_body<BM, BN, RELU>(A, B, bias, C, M, N, K, K,
                            blockIdx.y * BM, blockIdx.x * BN, 1, As, Bs);
}

// Split-K=2 GEMM in ONE launch: grid(z=2). kz=0 -> C0 (+bias), kz=1 -> C1 (no bias).
template<int BM, int BN>
__global__ __launch_bounds__(256) void gemm_sk2_kernel(
    const float* __restrict__ A, const float* __restrict__ B,
    const float* __restrict__ bias, float* __restrict__ C0, float* __restrict__ C1,
    int M, int N, int Kfull)
{
    __shared__ float As[2][BM][20];
    __shared__ float Bs[2][16][BN + 4];
    const int kz = blockIdx.z;
    const int Kh = Kfull >> 1;
    gemm_body<BM, BN, 0>(A + (size_t)kz * Kh, B + (size_t)kz * Kh * N,
                         bias, kz ? C1 : C0, M, N, Kh, Kfull,
                         blockIdx.y * BM, blockIdx.x * BN, kz == 0, As, Bs);
}

// Fused val/off/attn: 5 N-tiles (val:2, off:2, attn:1) x 121 M-blocks = 605 blocks.
struct MG3 {
    const float* A[3];
    const float* B[3];
    const float* bias[3];
    float* C[3];
    int N[3];
};

__global__ __launch_bounds__(256) void gemm3_kernel(MG3 mg, int M, int K)
{
    constexpr int BM = 64, BN = 128;
    __shared__ float As[2][BM][20];
    __shared__ float Bs[2][16][BN + 4];
    const int bx  = blockIdx.x;                       // 0..4
    const int gid = (bx < 2) ? 0 : (bx < 4) ? 1 : 2;
    const int nb  = (bx == 1 || bx == 3) ? 1 : 0;
    gemm_body<BM, BN, 0>(mg.A[gid], mg.B[gid], mg.bias[gid], mg.C[gid],
                         M, mg.N[gid], K, K,
                         blockIdx.y * BM, nb * BN, 1, As, Bs);
}

// ---------------- MSDA: metadata phase + gather phase, one block per s ----
__global__ __launch_bounds__(256) void msda_kernel(
    const float* __restrict__ val, const float* __restrict__ off,
    const float* __restrict__ attn, const float* __restrict__ vr,
    float* __restrict__ out)
{
    const unsigned FULL = 0xffffffffu;
    const int s   = blockIdx.x;
    const int tid = threadIdx.x;

    __shared__ float4 smw[128];   // per (m,p): 4 corner weights (aw*valid folded in)
    __shared__ uint2  smi[128];   // per (m,p): 4 global row indices, 2x16-bit packed

    if (tid < 128) {
        const int m   = tid >> 4;
        const int p   = tid & 15;       // p = lvl*4 + pt
        const int lvl = p >> 2;
        const int pt  = p & 3;

        // softmax over 16 logits within the 16-lane segment
        float logit = attn[(size_t)s * 128 + m * 16 + p];
        float mx = logit;
        #pragma unroll
        for (int o = 8; o > 0; o >>= 1) mx = fmaxf(mx, __shfl_xor_sync(FULL, mx, o));
        float e = expf(logit - mx);
        float sum = e;
        #pragma unroll
        for (int o = 8; o > 0; o >>= 1) sum += __shfl_xor_sync(FULL, sum, o);
        float aw = e / sum;

        // reference point of query s (unnormalized base)
        int lvlS = (s >= 7581) ? 3 : (s >= 7220) ? 2 : (s >= 5776) ? 1 : 0;
        int idxS = s - c_ST[lvlS];
        int Ws = c_W[lvlS], Hs = c_H[lvlS];
        int rowS = idxS / Ws, colS = idxS - rowS * Ws;
        float bx = (colS + 0.5f) / (vr[lvlS * 2 + 0] * (float)Ws);
        float by = (rowS + 0.5f) / (vr[lvlS * 2 + 1] * (float)Hs);

        const int H = c_H[lvl], W = c_W[lvl], st = c_ST[lvl];
        float refx = bx * vr[lvl * 2 + 0];
        float refy = by * vr[lvl * 2 + 1];
        float ox = off[(size_t)s * 256 + m * 32 + lvl * 8 + pt * 2 + 0];
        float oy = off[(size_t)s * 256 + m * 32 + lvl * 8 + pt * 2 + 1];

        // match reference arithmetic order
        float lx = refx + ox / (float)W;
        float ly = refy + oy / (float)H;
        float x = lx * (float)W - 0.5f;
        float y = ly * (float)H - 0.5f;
        float x0f = floorf(x), y0f = floorf(y);
        int x0 = (int)x0f, y0 = (int)y0f;
        float dx = x - x0f, dy = y - y0f;

        bool vx0 = (x0 >= 0) & (x0 < W);
        bool vx1 = (x0 + 1 >= 0) & (x0 + 1 < W);
        bool vy0 = (y0 >= 0) & (y0 < H);
        bool vy1 = (y0 + 1 >= 0) & (y0 + 1 < H);

        float w00 = (vy0 && vx0) ? aw * (1.f - dy) * (1.f - dx) : 0.f;
        float w01 = (vy0 && vx1) ? aw * (1.f - dy) * dx          : 0.f;
        float w10 = (vy1 && vx0) ? aw * dy * (1.f - dx)          : 0.f;
        float w11 = (vy1 && vx1) ? aw * dy * dx                  : 0.f;

        int xi0 = min(max(x0, 0), W - 1);
        int xi1 = min(max(x0 + 1, 0), W - 1);
        int yi0 = min(max(y0, 0), H - 1);
        int yi1 = min(max(y0 + 1, 0), H - 1);

        uint32_t i00 = (uint32_t)(st + yi0 * W + xi0);
        uint32_t i01 = (uint32_t)(st + yi0 * W + xi1);
        uint32_t i10 = (uint32_t)(st + yi1 * W + xi0);
        uint32_t i11 = (uint32_t)(st + yi1 * W + xi1);

        smw[tid] = make_float4(w00, w01, w10, w11);
        smi[tid] = make_uint2(i00 | (i01 << 16), i10 | (i11 << 16));
    }
    __syncthreads();

    // gather: warp = head, lane = channel
    const int m = tid >> 5;
    const int lane = tid & 31;
    const float* vb = val + m * 32 + lane;
    float acc = 0.f;
    #pragma unroll
    for (int p = 0; p < 16; p++) {
        float4 w = smw[m * 16 + p];
        uint2 ii = smi[m * 16 + p];
        acc += w.x * vb[(size_t)(ii.x & 0xffffu) * 256];
        acc += w.y * vb[(size_t)(ii.x >> 16)     * 256];
        acc += w.z * vb[(size_t)(ii.y & 0xffffu) * 256];
        acc += w.w * vb[(size_t)(ii.y >> 16)     * 256];
    }
    out[(size_t)s * 256 + m * 32 + lane] = acc;
}

// ---------------- residual + split-K partials + LayerNorm (in place) ------
__device__ __forceinline__ float block_sum(float v) {
    __shared__ float sh[8];
    int lane = threadIdx.x & 31, wid = threadIdx.x >> 5;
    #pragma unroll
    for (int o = 16; o > 0; o >>= 1) v += __shfl_xor_sync(0xffffffffu, v, o);
    if (lane == 0) sh[wid] = v;
    __syncthreads();
    if (wid == 0) {
        float t = (lane < 8) ? sh[lane] : 0.f;
        #pragma unroll
        for (int o = 4; o > 0; o >>= 1) t += __shfl_xor_sync(0xffffffffu, t, o);
        if (lane == 0) sh[0] = t;
    }
    __syncthreads();
    float r = sh[0];
    __syncthreads();
    return r;
}

__global__ __launch_bounds__(256) void add3_ln_kernel(
    float* __restrict__ x, const float* __restrict__ p0, const float* __restrict__ p1,
    const float* __restrict__ g, const float* __restrict__ b)
{
    int s = blockIdx.x;
    int t = threadIdx.x;
    size_t i = (size_t)s * 256 + t;
    float v = x[i] + (p0[i] + p1[i]);
    float mean = block_sum(v) * (1.f / 256.f);
    float d = v - mean;
    float var = block_sum(d * d) * (1.f / 256.f);
    float inv = rsqrtf(var + 1e-5f);
    x[i] = d * inv * g[t] + b[t];
}

// ---------------- launch --------------------------------------------------
extern "C" void kernel_launch(void* const* d_in, const int* in_sizes, int n_in,
                              void* d_out, int out_size) {
    const float* src    = (const float*)d_in[0];
    const float* pos    = (const float*)d_in[1];
    const float* vr     = (const float*)d_in[2];
    const float* W_off  = (const float*)d_in[6];
    const float* b_off  = (const float*)d_in[7];
    const float* W_attn = (const float*)d_in[8];
    const float* b_attn = (const float*)d_in[9];
    const float* W_val  = (const float*)d_in[10];
    const float* b_val  = (const float*)d_in[11];
    const float* W_out  = (const float*)d_in[12];
    const float* b_out  = (const float*)d_in[13];
    const float* ln1_g  = (const float*)d_in[14];
    const float* ln1_b  = (const float*)d_in[15];
    const float* W_ff1  = (const float*)d_in[16];
    const float* b_ff1  = (const float*)d_in[17];
    const float* W_ff2  = (const float*)d_in[18];
    const float* b_ff2  = (const float*)d_in[19];
    const float* ln2_g  = (const float*)d_in[20];
    const float* ln2_b  = (const float*)d_in[21];

    float* x = (float*)d_out;   // running activation, ends as the output

    float *q, *val, *off, *attn, *samp, *tmp, *tmp2, *ffh;
    cudaGetSymbolAddress((void**)&q,    g_q);
    cudaGetSymbolAddress((void**)&val,  g_val);
    cudaGetSymbolAddress((void**)&off,  g_off);
    cudaGetSymbolAddress((void**)&attn, g_attn);
    cudaGetSymbolAddress((void**)&samp, g_samp);
    cudaGetSymbolAddress((void**)&tmp,  g_tmp);
    cudaGetSymbolAddress((void**)&tmp2, g_tmp2);
    cudaGetSymbolAddress((void**)&ffh,  g_ffh);

    const int S = S_TOT;
    const int MB64  = 121;                    // ceil(7681/64)
    const int MB128 = 61;                     // ceil(7681/128)
    const dim3 g3(5, MB64);                   // fused val/off/attn: 605 blocks
    const dim3 gsk(2, MB64, 2);               // split-K=2, N=256: 484 blocks
    const dim3 g1024(8, MB128);               // ff1: 488 blocks

    copy_kernel<<<S, 256>>>(x, src);

    for (int l = 0; l < 3; l++) {
        add_kernel<<<S, 256>>>(q, x, pos);

        MG3 mg;
        mg.A[0] = x;    mg.B[0] = W_val  + (size_t)l * 65536; mg.bias[0] = b_val  + l * 256; mg.C[0] = val;  mg.N[0] = 256;
        mg.A[1] = q;    mg.B[1] = W_off  + (size_t)l * 65536; mg.bias[1] = b_off  + l * 256; mg.C[1] = off;  mg.N[1] = 256;
        mg.A[2] = q;    mg.B[2] = W_attn + (size_t)l * 32768; mg.bias[2] = b_attn + l * 128; mg.C[2] = attn; mg.N[2] = 128;
        gemm3_kernel<<<g3, 256>>>(mg, S, 256);

        msda_kernel<<<S, 256>>>(val, off, attn, vr, samp);

        gemm_sk2_kernel<64, 128><<<gsk, 256>>>(samp, W_out + (size_t)l * 65536,
                                               b_out + l * 256, tmp, tmp2, S, 256, 256);
        add3_ln_kernel<<<S, 256>>>(x, tmp, tmp2, ln1_g + l * 256, ln1_b + l * 256);

        gemm_tf32_kernel<128, 128, 1><<<g1024, 256>>>(x, W_ff1 + (size_t)l * 262144,
                                                      b_ff1 + l * 1024, ffh, S, 1024, 256);
        gemm_sk2_kernel<64, 128><<<gsk, 256>>>(ffh, W_ff2 + (size_t)l * 262144,
                                               b_ff2 + l * 256, tmp, tmp2, S, 256, 1024);
        add3_ln_kernel<<<S, 256>>>(x, tmp, tmp2, ln2_g + l * 256, ln2_b + l * 256);
    }
}

// round 9
// speedup vs baseline: 1.6038x; 1.6038x over previous
#include <cuda_runtime.h>
#include <math.h>
#include <stdint.h>

#define S_TOT 7681
#define C_DIM 256

// ---------------- scratch (static device globals; no allocation) ----------
__device__ float g_q   [S_TOT * C_DIM];
__device__ float g_val [S_TOT * C_DIM];
__device__ float g_off [S_TOT * C_DIM];
__device__ float g_attn[S_TOT * 128];
__device__ float g_samp[S_TOT * C_DIM];
__device__ float g_tmp [S_TOT * C_DIM];
__device__ float g_tmp2[S_TOT * C_DIM];
__device__ float g_ffh [S_TOT * 1024];

__constant__ int c_H [4] = {76, 38, 19, 10};
__constant__ int c_W [4] = {76, 38, 19, 10};
__constant__ int c_ST[4] = {0, 5776, 7220, 7581};

// ---------------- elementwise -------------------------------------------
// x = src; q = src + pos  (layer-0 query prep fused into the init copy)
__global__ __launch_bounds__(256) void copy2_kernel(float* __restrict__ x,
                                                    float* __restrict__ q,
                                                    const float* __restrict__ src,
                                                    const float* __restrict__ pos) {
    int i = blockIdx.x * 256 + threadIdx.x;
    float v = src[i];
    x[i] = v;
    q[i] = v + pos[i];
}

// ---------------- tf32 tensor-core GEMM primitives ------------------------
__device__ __forceinline__ void cp16(uint32_t s, const void* g) {
    asm volatile("cp.async.cg.shared.global [%0], [%1], 16;" :: "r"(s), "l"(g) : "memory");
}

__device__ __forceinline__ void mma8(float c[4], const uint32_t a[4], const uint32_t b[2]) {
    asm volatile(
        "mma.sync.aligned.m16n8k8.row.col.f32.tf32.tf32.f32 "
        "{%0,%1,%2,%3}, {%4,%5,%6,%7}, {%8,%9}, {%0,%1,%2,%3};"
        : "+f"(c[0]), "+f"(c[1]), "+f"(c[2]), "+f"(c[3])
        : "r"(a[0]), "r"(a[1]), "r"(a[2]), "r"(a[3]), "r"(b[0]), "r"(b[1]));
}

// Core mainloop + epilogue, shared by all GEMM kernels.
template<int BM, int BN, int RELU>
__device__ __forceinline__ void gemm_body(
    const float* __restrict__ A, const float* __restrict__ B,
    const float* __restrict__ bias, float* __restrict__ C,
    int M, int N, int K, int lda, int m0, int n0, int use_bias,
    float (*As)[BM][20], float (*Bs)[16][BN + 4])
{
    constexpr int BK = 16;
    constexpr int WM = BM / 32;
    constexpr int WN = 8 / WM;
    constexpr int NT = BN / (WN * 8);
    constexpr int BROW = BN / 4;
    constexpr int A_ITERS = BM * 4 / 256;
    constexpr int B_ITERS = BN / 64;

    const int tid  = threadIdx.x;
    const int lane = tid & 31;
    const int wid  = tid >> 5;
    const int wm   = wid % WM;
    const int wn   = wid / WM;

    float acc[2][NT][4];
    #pragma unroll
    for (int mt = 0; mt < 2; mt++)
        #pragma unroll
        for (int nt = 0; nt < NT; nt++)
            #pragma unroll
            for (int j = 0; j < 4; j++) acc[mt][nt][j] = 0.f;

    auto prefetch = [&](int buf, int k0) {
        #pragma unroll
        for (int i = 0; i < A_ITERS; i++) {
            int f = tid + i * 256;
            int r = f >> 2, c = (f & 3) * 4;
            int gm = m0 + r; if (gm > M - 1) gm = M - 1;
            cp16((uint32_t)__cvta_generic_to_shared(&As[buf][r][c]),
                 A + (size_t)gm * lda + k0 + c);
        }
        #pragma unroll
        for (int i = 0; i < B_ITERS; i++) {
            int f = tid + i * 256;
            int r = f / BROW, c = (f % BROW) * 4;
            cp16((uint32_t)__cvta_generic_to_shared(&Bs[buf][r][c]),
                 B + (size_t)(k0 + r) * N + n0 + c);
        }
        asm volatile("cp.async.commit_group;" ::: "memory");
    };

    prefetch(0, 0);
    int buf = 0;
    for (int k0 = 0; k0 < K; k0 += BK) {
        const bool has_next = (k0 + BK) < K;
        if (has_next) {
            prefetch(buf ^ 1, k0 + BK);
            asm volatile("cp.async.wait_group 1;" ::: "memory");
        } else {
            asm volatile("cp.async.wait_group 0;" ::: "memory");
        }
        __syncthreads();

        #pragma unroll
        for (int kc = 0; kc < BK; kc += 8) {
            const int mb = wm * 32 + (lane >> 2);
            const int kk = kc + (lane & 3);
            uint32_t afr[2][4];
            #pragma unroll
            for (int mt = 0; mt < 2; mt++) {
                afr[mt][0] = __float_as_uint(As[buf][mb + mt * 16    ][kk]);
                afr[mt][1] = __float_as_uint(As[buf][mb + mt * 16 + 8][kk]);
                afr[mt][2] = __float_as_uint(As[buf][mb + mt * 16    ][kk + 4]);
                afr[mt][3] = __float_as_uint(As[buf][mb + mt * 16 + 8][kk + 4]);
            }
            uint32_t bfr[NT][2];
            #pragma unroll
            for (int nt = 0; nt < NT; nt++) {
                const int kr = kc + (lane & 3);
                const int nc = wn * (BN / WN) + nt * 8 + (lane >> 2);
                bfr[nt][0] = __float_as_uint(Bs[buf][kr    ][nc]);
                bfr[nt][1] = __float_as_uint(Bs[buf][kr + 4][nc]);
            }
            #pragma unroll
            for (int mt = 0; mt < 2; mt++)
                #pragma unroll
                for (int nt = 0; nt < NT; nt++)
                    mma8(acc[mt][nt], afr[mt], bfr[nt]);
        }
        __syncthreads();
        buf ^= 1;
    }

    #pragma unroll
    for (int mt = 0; mt < 2; mt++) {
        int gm = m0 + wm * 32 + mt * 16 + (lane >> 2);
        #pragma unroll
        for (int nt = 0; nt < NT; nt++) {
            int gn = n0 + wn * (BN / WN) + nt * 8 + 2 * (lane & 3);
            float b0 = 0.f, b1 = 0.f;
            if (use_bias) { b0 = bias[gn]; b1 = bias[gn + 1]; }
            float v0 = acc[mt][nt][0] + b0, v1 = acc[mt][nt][1] + b1;
            float v2 = acc[mt][nt][2] + b0, v3 = acc[mt][nt][3] + b1;
            if (RELU) {
                v0 = fmaxf(v0, 0.f); v1 = fmaxf(v1, 0.f);
                v2 = fmaxf(v2, 0.f); v3 = fmaxf(v3, 0.f);
            }
            if (gm < M)
                *reinterpret_cast<float2*>(C + (size_t)gm * N + gn) = make_float2(v0, v1);
            if (gm + 8 < M)
                *reinterpret_cast<float2*>(C + (size_t)(gm + 8) * N + gn) = make_float2(v2, v3);
        }
    }
}

// Plain GEMM (used for ff1): C = A@B + bias (+relu)
template<int BM, int BN, int RELU>
__global__ __launch_bounds__(256) void gemm_tf32_kernel(
    const float* __restrict__ A, const float* __restrict__ B,
    const float* __restrict__ bias, float* __restrict__ C,
    int M, int N, int K)
{
    __shared__ float As[2][BM][20];
    __shared__ float Bs[2][16][BN + 4];
    gemm_body<BM, BN, RELU>(A, B, bias, C, M, N, K, K,
                            blockIdx.y * BM, blockIdx.x * BN, 1, As, Bs);
}

// Split-K=2 GEMM in ONE launch: grid(z=2). kz=0 -> C0 (+bias), kz=1 -> C1 (no bias).
template<int BM, int BN>
__global__ __launch_bounds__(256) void gemm_sk2_kernel(
    const float* __restrict__ A, const float* __restrict__ B,
    const float* __restrict__ bias, float* __restrict__ C0, float* __restrict__ C1,
    int M, int N, int Kfull)
{
    __shared__ float As[2][BM][20];
    __shared__ float Bs[2][16][BN + 4];
    const int kz = blockIdx.z;
    const int Kh = Kfull >> 1;
    gemm_body<BM, BN, 0>(A + (size_t)kz * Kh, B + (size_t)kz * Kh * N,
                         bias, kz ? C1 : C0, M, N, Kh, Kfull,
                         blockIdx.y * BM, blockIdx.x * BN, kz == 0, As, Bs);
}

// Fused val/off/attn: 5 N-tiles (val:2, off:2, attn:1) x 121 M-blocks = 605 blocks.
struct MG3 {
    const float* A[3];
    const float* B[3];
    const float* bias[3];
    float* C[3];
    int N[3];
};

__global__ __launch_bounds__(256) void gemm3_kernel(MG3 mg, int M, int K)
{
    constexpr int BM = 64, BN = 128;
    __shared__ float As[2][BM][20];
    __shared__ float Bs[2][16][BN + 4];
    const int bx  = blockIdx.x;                       // 0..4
    const int gid = (bx < 2) ? 0 : (bx < 4) ? 1 : 2;
    const int nb  = (bx == 1 || bx == 3) ? 1 : 0;
    gemm_body<BM, BN, 0>(mg.A[gid], mg.B[gid], mg.bias[gid], mg.C[gid],
                         M, mg.N[gid], K, K,
                         blockIdx.y * BM, nb * BN, 1, As, Bs);
}

// ---------------- MSDA: metadata + float2 gather, one 128-thread block/s --
__global__ __launch_bounds__(128) void msda_kernel(
    const float* __restrict__ val, const float* __restrict__ off,
    const float* __restrict__ attn, const float* __restrict__ vr,
    float* __restrict__ out)
{
    const unsigned FULL = 0xffffffffu;
    const int s   = blockIdx.x;
    const int tid = threadIdx.x;

    __shared__ float4 smw[128];   // per (m,p): 4 corner weights (aw*valid folded in)
    __shared__ uint4  smi[128];   // per (m,p): 4 row byte-offsets (idx*1024)

    {
        const int m   = tid >> 4;
        const int p   = tid & 15;       // p = lvl*4 + pt
        const int lvl = p >> 2;
        const int pt  = p & 3;

        // softmax over the 16-logit segment (half-warp shuffles)
        float logit = attn[(size_t)s * 128 + m * 16 + p];
        float mx = logit;
        #pragma unroll
        for (int o = 8; o > 0; o >>= 1) mx = fmaxf(mx, __shfl_xor_sync(FULL, mx, o));
        float e = expf(logit - mx);
        float sum = e;
        #pragma unroll
        for (int o = 8; o > 0; o >>= 1) sum += __shfl_xor_sync(FULL, sum, o);
        float aw = e / sum;

        // reference point of query s
        int lvlS = (s >= 7581) ? 3 : (s >= 7220) ? 2 : (s >= 5776) ? 1 : 0;
        int idxS = s - c_ST[lvlS];
        int Ws = c_W[lvlS], Hs = c_H[lvlS];
        int rowS = idxS / Ws, colS = idxS - rowS * Ws;
        float bx = (colS + 0.5f) / (vr[lvlS * 2 + 0] * (float)Ws);
        float by = (rowS + 0.5f) / (vr[lvlS * 2 + 1] * (float)Hs);

        const int H = c_H[lvl], W = c_W[lvl], st = c_ST[lvl];
        float refx = bx * vr[lvl * 2 + 0];
        float refy = by * vr[lvl * 2 + 1];
        float ox = off[(size_t)s * 256 + m * 32 + lvl * 8 + pt * 2 + 0];
        float oy = off[(size_t)s * 256 + m * 32 + lvl * 8 + pt * 2 + 1];

        // match reference arithmetic order
        float lx = refx + ox / (float)W;
        float ly = refy + oy / (float)H;
        float x = lx * (float)W - 0.5f;
        float y = ly * (float)H - 0.5f;
        float x0f = floorf(x), y0f = floorf(y);
        int x0 = (int)x0f, y0 = (int)y0f;
        float dx = x - x0f, dy = y - y0f;

        bool vx0 = (x0 >= 0) & (x0 < W);
        bool vx1 = (x0 + 1 >= 0) & (x0 + 1 < W);
        bool vy0 = (y0 >= 0) & (y0 < H);
        bool vy1 = (y0 + 1 >= 0) & (y0 + 1 < H);

        float w00 = (vy0 && vx0) ? aw * (1.f - dy) * (1.f - dx) : 0.f;
        float w01 = (vy0 && vx1) ? aw * (1.f - dy) * dx          : 0.f;
        float w10 = (vy1 && vx0) ? aw * dy * (1.f - dx)          : 0.f;
        float w11 = (vy1 && vx1) ? aw * dy * dx                  : 0.f;

        int xi0 = min(max(x0, 0), W - 1);
        int xi1 = min(max(x0 + 1, 0), W - 1);
        int yi0 = min(max(y0, 0), H - 1);
        int yi1 = min(max(y0 + 1, 0), H - 1);

        smw[tid] = make_float4(w00, w01, w10, w11);
        smi[tid] = make_uint4((uint32_t)(st + yi0 * W + xi0) << 10,
                              (uint32_t)(st + yi0 * W + xi1) << 10,
                              (uint32_t)(st + yi1 * W + xi0) << 10,
                              (uint32_t)(st + yi1 * W + xi1) << 10);
    }
    __syncthreads();

    // gather: 16 threads per head, each handles 2 channels (float2)
    const int m  = tid >> 4;
    const int c2 = tid & 15;
    const char* vb = (const char*)val + (size_t)(m * 32 + c2 * 2) * sizeof(float);
    float accx = 0.f, accy = 0.f;
    #pragma unroll
    for (int p = 0; p < 16; p++) {
        float4 w = smw[m * 16 + p];
        uint4 ii = smi[m * 16 + p];
        float2 v0 = *reinterpret_cast<const float2*>(vb + ii.x);
        float2 v1 = *reinterpret_cast<const float2*>(vb + ii.y);
        float2 v2 = *reinterpret_cast<const float2*>(vb + ii.z);
        float2 v3 = *reinterpret_cast<const float2*>(vb + ii.w);
        accx += w.x * v0.x; accy += w.x * v0.y;
        accx += w.y * v1.x; accy += w.y * v1.y;
        accx += w.z * v2.x; accy += w.z * v2.y;
        accx += w.w * v3.x; accy += w.w * v3.y;
    }
    *reinterpret_cast<float2*>(out + (size_t)s * 256 + m * 32 + c2 * 2) =
        make_float2(accx, accy);
}

// ---------------- residual + split-K partials + LayerNorm (in place) ------
__device__ __forceinline__ float block_sum(float v) {
    __shared__ float sh[8];
    int lane = threadIdx.x & 31, wid = threadIdx.x >> 5;
    #pragma unroll
    for (int o = 16; o > 0; o >>= 1) v += __shfl_xor_sync(0xffffffffu, v, o);
    if (lane == 0) sh[wid] = v;
    __syncthreads();
    if (wid == 0) {
        float t = (lane < 8) ? sh[lane] : 0.f;
        #pragma unroll
        for (int o = 4; o > 0; o >>= 1) t += __shfl_xor_sync(0xffffffffu, t, o);
        if (lane == 0) sh[0] = t;
    }
    __syncthreads();
    float r = sh[0];
    __syncthreads();
    return r;
}

// x = LN(x + p0 + p1); optionally q = x_new + pos (next layer's query)
__global__ __launch_bounds__(256) void add3_ln_kernel(
    float* __restrict__ x, const float* __restrict__ p0, const float* __restrict__ p1,
    const float* __restrict__ g, const float* __restrict__ b,
    const float* __restrict__ pos, float* __restrict__ qout)
{
    int s = blockIdx.x;
    int t = threadIdx.x;
    size_t i = (size_t)s * 256 + t;
    float v = x[i] + (p0[i] + p1[i]);
    float mean = block_sum(v) * (1.f / 256.f);
    float d = v - mean;
    float var = block_sum(d * d) * (1.f / 256.f);
    float inv = rsqrtf(var + 1e-5f);
    float r = d * inv * g[t] + b[t];
    x[i] = r;
    if (qout) qout[i] = r + pos[i];
}

// ---------------- launch --------------------------------------------------
extern "C" void kernel_launch(void* const* d_in, const int* in_sizes, int n_in,
                              void* d_out, int out_size) {
    const float* src    = (const float*)d_in[0];
    const float* pos    = (const float*)d_in[1];
    const float* vr     = (const float*)d_in[2];
    const float* W_off  = (const float*)d_in[6];
    const float* b_off  = (const float*)d_in[7];
    const float* W_attn = (const float*)d_in[8];
    const float* b_attn = (const float*)d_in[9];
    const float* W_val  = (const float*)d_in[10];
    const float* b_val  = (const float*)d_in[11];
    const float* W_out  = (const float*)d_in[12];
    const float* b_out  = (const float*)d_in[13];
    const float* ln1_g  = (const float*)d_in[14];
    const float* ln1_b  = (const float*)d_in[15];
    const float* W_ff1  = (const float*)d_in[16];
    const float* b_ff1  = (const float*)d_in[17];
    const float* W_ff2  = (const float*)d_in[18];
    const float* b_ff2  = (const float*)d_in[19];
    const float* ln2_g  = (const float*)d_in[20];
    const float* ln2_b  = (const float*)d_in[21];

    float* x = (float*)d_out;   // running activation, ends as the output

    float *q, *val, *off, *attn, *samp, *tmp, *tmp2, *ffh;
    cudaGetSymbolAddress((void**)&q,    g_q);
    cudaGetSymbolAddress((void**)&val,  g_val);
    cudaGetSymbolAddress((void**)&off,  g_off);
    cudaGetSymbolAddress((void**)&attn, g_attn);
    cudaGetSymbolAddress((void**)&samp, g_samp);
    cudaGetSymbolAddress((void**)&tmp,  g_tmp);
    cudaGetSymbolAddress((void**)&tmp2, g_tmp2);
    cudaGetSymbolAddress((void**)&ffh,  g_ffh);

    const int S = S_TOT;
    const int MB64  = 121;                    // ceil(7681/64)
    const int MB128 = 61;                     // ceil(7681/128)
    const dim3 g3(5, MB64);                   // fused val/off/attn: 605 blocks
    const dim3 gsk(2, MB64, 2);               // split-K=2, N=256: 484 blocks
    const dim3 g1024(8, MB128);               // ff1: 488 blocks

    copy2_kernel<<<S, 256>>>(x, q, src, pos);

    for (int l = 0; l < 3; l++) {
        MG3 mg;
        mg.A[0] = x;    mg.B[0] = W_val  + (size_t)l * 65536; mg.bias[0] = b_val  + l * 256; mg.C[0] = val;  mg.N[0] = 256;
        mg.A[1] = q;    mg.B[1] = W_off  + (size_t)l * 65536; mg.bias[1] = b_off  + l * 256; mg.C[1] = off;  mg.N[1] = 256;
        mg.A[2] = q;    mg.B[2] = W_attn + (size_t)l * 32768; mg.bias[2] = b_attn + l * 128; mg.C[2] = attn; mg.N[2] = 128;
        gemm3_kernel<<<g3, 256>>>(mg, S, 256);

        msda_kernel<<<S, 128>>>(val, off, attn, vr, samp);

        gemm_sk2_kernel<64, 128><<<gsk, 256>>>(samp, W_out + (size_t)l * 65536,
                                               b_out + l * 256, tmp, tmp2, S, 256, 256);
        add3_ln_kernel<<<S, 256>>>(x, tmp, tmp2, ln1_g + l * 256, ln1_b + l * 256,
                                   nullptr, nullptr);

        gemm_tf32_kernel<128, 128, 1><<<g1024, 256>>>(x, W_ff1 + (size_t)l * 262144,
                                                      b_ff1 + l * 1024, ffh, S, 1024, 256);
        gemm_sk2_kernel<64, 128><<<gsk, 256>>>(ffh, W_ff2 + (size_t)l * 262144,
                                               b_ff2 + l * 256, tmp, tmp2, S, 256, 1024);
        // last layer: q not needed, skip the extra write
        add3_ln_kernel<<<S, 256>>>(x, tmp, tmp2, ln2_g + l * 256, ln2_b + l * 256,
                                   (l < 2) ? pos : nullptr, (l < 2) ? q : nullptr);
    }
}

// round 10
// speedup vs baseline: 1.6326x; 1.0180x over previous
#include <cuda_runtime.h>
#include <math.h>
#include <stdint.h>

#define S_TOT 7681
#define C_DIM 256

// ---------------- scratch (static device globals; no allocation) ----------
__device__ float g_q   [S_TOT * C_DIM];
__device__ float g_val [S_TOT * C_DIM];
__device__ float g_off [S_TOT * C_DIM];
__device__ float g_attn[S_TOT * 128];
__device__ float g_samp[S_TOT * C_DIM];
__device__ float g_tmp [S_TOT * C_DIM];
__device__ float g_tmp2[S_TOT * C_DIM];
__device__ float g_ffh [S_TOT * 1024];

__constant__ int c_H [4] = {76, 38, 19, 10};
__constant__ int c_W [4] = {76, 38, 19, 10};
__constant__ int c_ST[4] = {0, 5776, 7220, 7581};

// ---------------- elementwise -------------------------------------------
// x = src; q = src + pos  (layer-0 query prep fused into the init copy)
__global__ __launch_bounds__(256) void copy2_kernel(float* __restrict__ x,
                                                    float* __restrict__ q,
                                                    const float* __restrict__ src,
                                                    const float* __restrict__ pos) {
    int i = blockIdx.x * 256 + threadIdx.x;
    float v = src[i];
    x[i] = v;
    q[i] = v + pos[i];
}

// ---------------- tf32 tensor-core GEMM primitives ------------------------
__device__ __forceinline__ void cp16(uint32_t s, const void* g) {
    asm volatile("cp.async.cg.shared.global [%0], [%1], 16;" :: "r"(s), "l"(g) : "memory");
}

__device__ __forceinline__ void mma8(float c[4], const uint32_t a[4], const uint32_t b[2]) {
    asm volatile(
        "mma.sync.aligned.m16n8k8.row.col.f32.tf32.tf32.f32 "
        "{%0,%1,%2,%3}, {%4,%5,%6,%7}, {%8,%9}, {%0,%1,%2,%3};"
        : "+f"(c[0]), "+f"(c[1]), "+f"(c[2]), "+f"(c[3])
        : "r"(a[0]), "r"(a[1]), "r"(a[2]), "r"(a[3]), "r"(b[0]), "r"(b[1]));
}

// Core mainloop + epilogue, shared by all GEMM kernels.
// 3-stage cp.async pipeline, ONE __syncthreads per BK=16 iteration.
template<int BM, int BN, int RELU>
__device__ __forceinline__ void gemm_body(
    const float* __restrict__ A, const float* __restrict__ B,
    const float* __restrict__ bias, float* __restrict__ C,
    int M, int N, int K, int lda, int m0, int n0, int use_bias,
    float (*As)[BM][20], float (*Bs)[16][BN + 4])
{
    constexpr int BK = 16;
    constexpr int WM = BM / 32;
    constexpr int WN = 8 / WM;
    constexpr int NT = BN / (WN * 8);
    constexpr int BROW = BN / 4;
    constexpr int A_ITERS = BM * 4 / 256;
    constexpr int B_ITERS = BN / 64;

    const int tid  = threadIdx.x;
    const int lane = tid & 31;
    const int wid  = tid >> 5;
    const int wm   = wid % WM;
    const int wn   = wid / WM;

    float acc[2][NT][4];
    #pragma unroll
    for (int mt = 0; mt < 2; mt++)
        #pragma unroll
        for (int nt = 0; nt < NT; nt++)
            #pragma unroll
            for (int j = 0; j < 4; j++) acc[mt][nt][j] = 0.f;

    auto prefetch = [&](int buf, int k0) {
        #pragma unroll
        for (int i = 0; i < A_ITERS; i++) {
            int f = tid + i * 256;
            int r = f >> 2, c = (f & 3) * 4;
            int gm = m0 + r; if (gm > M - 1) gm = M - 1;
            cp16((uint32_t)__cvta_generic_to_shared(&As[buf][r][c]),
                 A + (size_t)gm * lda + k0 + c);
        }
        #pragma unroll
        for (int i = 0; i < B_ITERS; i++) {
            int f = tid + i * 256;
            int r = f / BROW, c = (f % BROW) * 4;
            cp16((uint32_t)__cvta_generic_to_shared(&Bs[buf][r][c]),
                 B + (size_t)(k0 + r) * N + n0 + c);
        }
        asm volatile("cp.async.commit_group;" ::: "memory");
    };

    // prologue: stages 0, 1 in flight
    prefetch(0, 0);
    if (BK < K) prefetch(1, BK);
    else        asm volatile("cp.async.commit_group;" ::: "memory"); // keep group count uniform

    int buf = 0;
    for (int k0 = 0; k0 < K; k0 += BK) {
        if (k0 + BK < K) asm volatile("cp.async.wait_group 1;" ::: "memory");
        else             asm volatile("cp.async.wait_group 0;" ::: "memory");
        __syncthreads();   // data of `buf` visible; all warps done with buf-1's compute

        if (k0 + 2 * BK < K) {
            int nb = buf + 2; if (nb >= 3) nb -= 3;
            prefetch(nb, k0 + 2 * BK);
        }

        #pragma unroll
        for (int kc = 0; kc < BK; kc += 8) {
            const int mb = wm * 32 + (lane >> 2);
            const int kk = kc + (lane & 3);
            uint32_t afr[2][4];
            #pragma unroll
            for (int mt = 0; mt < 2; mt++) {
                afr[mt][0] = __float_as_uint(As[buf][mb + mt * 16    ][kk]);
                afr[mt][1] = __float_as_uint(As[buf][mb + mt * 16 + 8][kk]);
                afr[mt][2] = __float_as_uint(As[buf][mb + mt * 16    ][kk + 4]);
                afr[mt][3] = __float_as_uint(As[buf][mb + mt * 16 + 8][kk + 4]);
            }
            uint32_t bfr[NT][2];
            #pragma unroll
            for (int nt = 0; nt < NT; nt++) {
                const int kr = kc + (lane & 3);
                const int nc = wn * (BN / WN) + nt * 8 + (lane >> 2);
                bfr[nt][0] = __float_as_uint(Bs[buf][kr    ][nc]);
                bfr[nt][1] = __float_as_uint(Bs[buf][kr + 4][nc]);
            }
            #pragma unroll
            for (int mt = 0; mt < 2; mt++)
                #pragma unroll
                for (int nt = 0; nt < NT; nt++)
                    mma8(acc[mt][nt], afr[mt], bfr[nt]);
        }
        buf++; if (buf >= 3) buf = 0;
    }

    #pragma unroll
    for (int mt = 0; mt < 2; mt++) {
        int gm = m0 + wm * 32 + mt * 16 + (lane >> 2);
        #pragma unroll
        for (int nt = 0; nt < NT; nt++) {
            int gn = n0 + wn * (BN / WN) + nt * 8 + 2 * (lane & 3);
            float b0 = 0.f, b1 = 0.f;
            if (use_bias) { b0 = bias[gn]; b1 = bias[gn + 1]; }
            float v0 = acc[mt][nt][0] + b0, v1 = acc[mt][nt][1] + b1;
            float v2 = acc[mt][nt][2] + b0, v3 = acc[mt][nt][3] + b1;
            if (RELU) {
                v0 = fmaxf(v0, 0.f); v1 = fmaxf(v1, 0.f);
                v2 = fmaxf(v2, 0.f); v3 = fmaxf(v3, 0.f);
            }
            if (gm < M)
                *reinterpret_cast<float2*>(C + (size_t)gm * N + gn) = make_float2(v0, v1);
            if (gm + 8 < M)
                *reinterpret_cast<float2*>(C + (size_t)(gm + 8) * N + gn) = make_float2(v2, v3);
        }
    }
}

// Plain GEMM (used for ff1): C = A@B + bias (+relu)
template<int BM, int BN, int RELU>
__global__ __launch_bounds__(256) void gemm_tf32_kernel(
    const float* __restrict__ A, const float* __restrict__ B,
    const float* __restrict__ bias, float* __restrict__ C,
    int M, int N, int K)
{
    __shared__ float As[3][BM][20];
    __shared__ float Bs[3][16][BN + 4];
    gemm_body<BM, BN, RELU>(A, B, bias, C, M, N, K, K,
                            blockIdx.y * BM, blockIdx.x * BN, 1, As, Bs);
}

// Split-K=2 GEMM in ONE launch: grid(z=2). kz=0 -> C0 (+bias), kz=1 -> C1 (no bias).
template<int BM, int BN>
__global__ __launch_bounds__(256) void gemm_sk2_kernel(
    const float* __restrict__ A, const float* __restrict__ B,
    const float* __restrict__ bias, float* __restrict__ C0, float* __restrict__ C1,
    int M, int N, int Kfull)
{
    __shared__ float As[3][BM][20];
    __shared__ float Bs[3][16][BN + 4];
    const int kz = blockIdx.z;
    const int Kh = Kfull >> 1;
    gemm_body<BM, BN, 0>(A + (size_t)kz * Kh, B + (size_t)kz * Kh * N,
                         bias, kz ? C1 : C0, M, N, Kh, Kfull,
                         blockIdx.y * BM, blockIdx.x * BN, kz == 0, As, Bs);
}

// Fused val/off/attn: 5 N-tiles (val:2, off:2, attn:1) x 121 M-blocks = 605 blocks.
struct MG3 {
    const float* A[3];
    const float* B[3];
    const float* bias[3];
    float* C[3];
    int N[3];
};

__global__ __launch_bounds__(256) void gemm3_kernel(MG3 mg, int M, int K)
{
    constexpr int BM = 64, BN = 128;
    __shared__ float As[3][BM][20];
    __shared__ float Bs[3][16][BN + 4];
    const int bx  = blockIdx.x;                       // 0..4
    const int gid = (bx < 2) ? 0 : (bx < 4) ? 1 : 2;
    const int nb  = (bx == 1 || bx == 3) ? 1 : 0;
    gemm_body<BM, BN, 0>(mg.A[gid], mg.B[gid], mg.bias[gid], mg.C[gid],
                         M, mg.N[gid], K, K,
                         blockIdx.y * BM, nb * BN, 1, As, Bs);
}

// ---------------- MSDA: metadata + float2 gather, one 128-thread block/s --
__global__ __launch_bounds__(128) void msda_kernel(
    const float* __restrict__ val, const float* __restrict__ off,
    const float* __restrict__ attn, const float* __restrict__ vr,
    float* __restrict__ out)
{
    const unsigned FULL = 0xffffffffu;
    const int s   = blockIdx.x;
    const int tid = threadIdx.x;

    __shared__ float4 smw[128];   // per (m,p): 4 corner weights (aw*valid folded in)
    __shared__ uint4  smi[128];   // per (m,p): 4 row byte-offsets (idx*1024)

    {
        const int m   = tid >> 4;
        const int p   = tid & 15;       // p = lvl*4 + pt
        const int lvl = p >> 2;
        const int pt  = p & 3;

        // softmax over the 16-logit segment (half-warp shuffles)
        float logit = attn[(size_t)s * 128 + m * 16 + p];
        float mx = logit;
        #pragma unroll
        for (int o = 8; o > 0; o >>= 1) mx = fmaxf(mx, __shfl_xor_sync(FULL, mx, o));
        float e = expf(logit - mx);
        float sum = e;
        #pragma unroll
        for (int o = 8; o > 0; o >>= 1) sum += __shfl_xor_sync(FULL, sum, o);
        float aw = e / sum;

        // reference point of query s
        int lvlS = (s >= 7581) ? 3 : (s >= 7220) ? 2 : (s >= 5776) ? 1 : 0;
        int idxS = s - c_ST[lvlS];
        int Ws = c_W[lvlS], Hs = c_H[lvlS];
        int rowS = idxS / Ws, colS = idxS - rowS * Ws;
        float bx = (colS + 0.5f) / (vr[lvlS * 2 + 0] * (float)Ws);
        float by = (rowS + 0.5f) / (vr[lvlS * 2 + 1] * (float)Hs);

        const int H = c_H[lvl], W = c_W[lvl], st = c_ST[lvl];
        float refx = bx * vr[lvl * 2 + 0];
        float refy = by * vr[lvl * 2 + 1];
        float ox = off[(size_t)s * 256 + m * 32 + lvl * 8 + pt * 2 + 0];
        float oy = off[(size_t)s * 256 + m * 32 + lvl * 8 + pt * 2 + 1];

        // match reference arithmetic order
        float lx = refx + ox / (float)W;
        float ly = refy + oy / (float)H;
        float x = lx * (float)W - 0.5f;
        float y = ly * (float)H - 0.5f;
        float x0f = floorf(x), y0f = floorf(y);
        int x0 = (int)x0f, y0 = (int)y0f;
        float dx = x - x0f, dy = y - y0f;

        bool vx0 = (x0 >= 0) & (x0 < W);
        bool vx1 = (x0 + 1 >= 0) & (x0 + 1 < W);
        bool vy0 = (y0 >= 0) & (y0 < H);
        bool vy1 = (y0 + 1 >= 0) & (y0 + 1 < H);

        float w00 = (vy0 && vx0) ? aw * (1.f - dy) * (1.f - dx) : 0.f;
        float w01 = (vy0 && vx1) ? aw * (1.f - dy) * dx          : 0.f;
        float w10 = (vy1 && vx0) ? aw * dy * (1.f - dx)          : 0.f;
        float w11 = (vy1 && vx1) ? aw * dy * dx                  : 0.f;

        int xi0 = min(max(x0, 0), W - 1);
        int xi1 = min(max(x0 + 1, 0), W - 1);
        int yi0 = min(max(y0, 0), H - 1);
        int yi1 = min(max(y0 + 1, 0), H - 1);

        smw[tid] = make_float4(w00, w01, w10, w11);
        smi[tid] = make_uint4((uint32_t)(st + yi0 * W + xi0) << 10,
                              (uint32_t)(st + yi0 * W + xi1) << 10,
                              (uint32_t)(st + yi1 * W + xi0) << 10,
                              (uint32_t)(st + yi1 * W + xi1) << 10);
    }
    __syncthreads();

    // gather: 16 threads per head, each handles 2 channels (float2)
    const int m  = tid >> 4;
    const int c2 = tid & 15;
    const char* vb = (const char*)val + (size_t)(m * 32 + c2 * 2) * sizeof(float);
    float accx = 0.f, accy = 0.f;
    #pragma unroll
    for (int p = 0; p < 16; p++) {
        float4 w = smw[m * 16 + p];
        uint4 ii = smi[m * 16 + p];
        float2 v0 = *reinterpret_cast<const float2*>(vb + ii.x);
        float2 v1 = *reinterpret_cast<const float2*>(vb + ii.y);
        float2 v2 = *reinterpret_cast<const float2*>(vb + ii.z);
        float2 v3 = *reinterpret_cast<const float2*>(vb + ii.w);
        accx += w.x * v0.x; accy += w.x * v0.y;
        accx += w.y * v1.x; accy += w.y * v1.y;
        accx += w.z * v2.x; accy += w.z * v2.y;
        accx += w.w * v3.x; accy += w.w * v3.y;
    }
    *reinterpret_cast<float2*>(out + (size_t)s * 256 + m * 32 + c2 * 2) =
        make_float2(accx, accy);
}

// ---------------- residual + split-K partials + LayerNorm (in place) ------
__device__ __forceinline__ float block_sum(float v) {
    __shared__ float sh[8];
    int lane = threadIdx.x & 31, wid = threadIdx.x >> 5;
    #pragma unroll
    for (int o = 16; o > 0; o >>= 1) v += __shfl_xor_sync(0xffffffffu, v, o);
    if (lane == 0) sh[wid] = v;
    __syncthreads();
    if (wid == 0) {
        float t = (lane < 8) ? sh[lane] : 0.f;
        #pragma unroll
        for (int o = 4; o > 0; o >>= 1) t += __shfl_xor_sync(0xffffffffu, t, o);
        if (lane == 0) sh[0] = t;
    }
    __syncthreads();
    float r = sh[0];
    __syncthreads();
    return r;
}

// x = LN(x + p0 + p1); optionally q = x_new + pos (next layer's query)
__global__ __launch_bounds__(256) void add3_ln_kernel(
    float* __restrict__ x, const float* __restrict__ p0, const float* __restrict__ p1,
    const float* __restrict__ g, const float* __restrict__ b,
    const float* __restrict__ pos, float* __restrict__ qout)
{
    int s = blockIdx.x;
    int t = threadIdx.x;
    size_t i = (size_t)s * 256 + t;
    float v = x[i] + (p0[i] + p1[i]);
    float mean = block_sum(v) * (1.f / 256.f);
    float d = v - mean;
    float var = block_sum(d * d) * (1.f / 256.f);
    float inv = rsqrtf(var + 1e-5f);
    float r = d * inv * g[t] + b[t];
    x[i] = r;
    if (qout) qout[i] = r + pos[i];
}

// ---------------- launch --------------------------------------------------
extern "C" void kernel_launch(void* const* d_in, const int* in_sizes, int n_in,
                              void* d_out, int out_size) {
    const float* src    = (const float*)d_in[0];
    const float* pos    = (const float*)d_in[1];
    const float* vr     = (const float*)d_in[2];
    const float* W_off  = (const float*)d_in[6];
    const float* b_off  = (const float*)d_in[7];
    const float* W_attn = (const float*)d_in[8];
    const float* b_attn = (const float*)d_in[9];
    const float* W_val  = (const float*)d_in[10];
    const float* b_val  = (const float*)d_in[11];
    const float* W_out  = (const float*)d_in[12];
    const float* b_out  = (const float*)d_in[13];
    const float* ln1_g  = (const float*)d_in[14];
    const float* ln1_b  = (const float*)d_in[15];
    const float* W_ff1  = (const float*)d_in[16];
    const float* b_ff1  = (const float*)d_in[17];
    const float* W_ff2  = (const float*)d_in[18];
    const float* b_ff2  = (const float*)d_in[19];
    const float* ln2_g  = (const float*)d_in[20];
    const float* ln2_b  = (const float*)d_in[21];

    float* x = (float*)d_out;   // running activation, ends as the output

    float *q, *val, *off, *attn, *samp, *tmp, *tmp2, *ffh;
    cudaGetSymbolAddress((void**)&q,    g_q);
    cudaGetSymbolAddress((void**)&val,  g_val);
    cudaGetSymbolAddress((void**)&off,  g_off);
    cudaGetSymbolAddress((void**)&attn, g_attn);
    cudaGetSymbolAddress((void**)&samp, g_samp);
    cudaGetSymbolAddress((void**)&tmp,  g_tmp);
    cudaGetSymbolAddress((void**)&tmp2, g_tmp2);
    cudaGetSymbolAddress((void**)&ffh,  g_ffh);

    const int S = S_TOT;
    const int MB64  = 121;                    // ceil(7681/64)
    const int MB128 = 61;                     // ceil(7681/128)
    const dim3 g3(5, MB64);                   // fused val/off/attn: 605 blocks
    const dim3 gsk(2, MB64, 2);               // split-K=2, N=256: 484 blocks
    const dim3 g1024(8, MB128);               // ff1: 488 blocks

    copy2_kernel<<<S, 256>>>(x, q, src, pos);

    for (int l = 0; l < 3; l++) {
        MG3 mg;
        mg.A[0] = x;    mg.B[0] = W_val  + (size_t)l * 65536; mg.bias[0] = b_val  + l * 256; mg.C[0] = val;  mg.N[0] = 256;
        mg.A[1] = q;    mg.B[1] = W_off  + (size_t)l * 65536; mg.bias[1] = b_off  + l * 256; mg.C[1] = off;  mg.N[1] = 256;
        mg.A[2] = q;    mg.B[2] = W_attn + (size_t)l * 32768; mg.bias[2] = b_attn + l * 128; mg.C[2] = attn; mg.N[2] = 128;
        gemm3_kernel<<<g3, 256>>>(mg, S, 256);

        msda_kernel<<<S, 128>>>(val, off, attn, vr, samp);

        gemm_sk2_kernel<64, 128><<<gsk, 256>>>(samp, W_out + (size_t)l * 65536,
                                               b_out + l * 256, tmp, tmp2, S, 256, 256);
        add3_ln_kernel<<<S, 256>>>(x, tmp, tmp2, ln1_g + l * 256, ln1_b + l * 256,
                                   nullptr, nullptr);

        gemm_tf32_kernel<128, 128, 1><<<g1024, 256>>>(x, W_ff1 + (size_t)l * 262144,
                                                      b_ff1 + l * 1024, ffh, S, 1024, 256);
        gemm_sk2_kernel<64, 128><<<gsk, 256>>>(ffh, W_ff2 + (size_t)l * 262144,
                                               b_ff2 + l * 256, tmp, tmp2, S, 256, 1024);
        // last layer: q not needed, skip the extra write
        add3_ln_kernel<<<S, 256>>>(x, tmp, tmp2, ln2_g + l * 256, ln2_b + l * 256,
                                   (l < 2) ? pos : nullptr, (l < 2) ? q : nullptr);
    }
}